// round 15
// baseline (speedup 1.0000x reference)
#include <cuda_runtime.h>
#include <cuda_fp16.h>
#include <cstdint>

#define NM 20000
#define ND 8000
#define NE 200000
#define FIN 384
#define HD 512
#define H1 512
#define OD 256

typedef __half  h16;
typedef __half2 h162;

// ---------------- scratch (device globals) ----------------
__device__ h16 g_mf[NM*FIN];
__device__ h16 g_df[ND*FIN];
__device__ h16 g_xm[NM*HD];
__device__ h16 g_xd[ND*HD];
__device__ h16 g_ad[ND*HD];
__device__ h16 g_ad2[ND*H1];
__device__ h16 g_hm[NM*H1];
__device__ h16 g_hd[ND*H1];
__device__ h16 g_qd[ND*H1];
__device__ float g_base[NM*H1];
__device__ h16 g_ud[ND*OD];
__device__ h16 g_wm[FIN*HD], g_wd[FIN*HD];
__device__ h16 g_w1mdl[HD*H1], g_w1mdr[HD*H1];
__device__ h16 g_w1dml[HD*H1], g_w1dmr[HD*H1];
__device__ h16 g_w2mdl[H1*OD], g_w2mdr[H1*OD];
__device__ h16 g_w2dml[H1*OD], g_w2dmr[H1*OD];
__device__ int g_cnt_m[NM], g_cnt_d[ND];
__device__ int g_off_m[NM+1], g_off_d[ND+1];
__device__ int g_cur_m[NM], g_cur_d[ND];
__device__ int g_csr_src[NE];
__device__ int g_csr_dst[NE];

// ---------------- PTX helpers ----------------
__device__ __forceinline__ void ldsm_x4(uint32_t& r0,uint32_t& r1,uint32_t& r2,uint32_t& r3,uint32_t a){
    asm volatile("ldmatrix.sync.aligned.m8n8.x4.shared.b16 {%0,%1,%2,%3},[%4];"
                 :"=r"(r0),"=r"(r1),"=r"(r2),"=r"(r3):"r"(a));
}
__device__ __forceinline__ void ldsm_x4t(uint32_t& r0,uint32_t& r1,uint32_t& r2,uint32_t& r3,uint32_t a){
    asm volatile("ldmatrix.sync.aligned.m8n8.x4.trans.shared.b16 {%0,%1,%2,%3},[%4];"
                 :"=r"(r0),"=r"(r1),"=r"(r2),"=r"(r3):"r"(a));
}
__device__ __forceinline__ void mma_f16(float* c, const uint32_t* a, uint32_t b0, uint32_t b1){
    asm volatile("mma.sync.aligned.m16n8k16.row.col.f32.f16.f16.f32 "
        "{%0,%1,%2,%3},{%4,%5,%6,%7},{%8,%9},{%0,%1,%2,%3};"
        :"+f"(c[0]),"+f"(c[1]),"+f"(c[2]),"+f"(c[3])
        :"r"(a[0]),"r"(a[1]),"r"(a[2]),"r"(a[3]),"r"(b0),"r"(b1));
}
__device__ __forceinline__ void cpa16(uint32_t d, const void* s, bool p){
    int sz = p ? 16 : 0;
    asm volatile("cp.async.cg.shared.global [%0],[%1],16,%2;"::"r"(d),"l"(s),"r"(sz));
}

// smem geometry (fp16 elements); 2-stage pipeline (R13-proven)
#define SA 40
#define SB 136
#define ASZ (128*SA)                 // 5120
#define BSZ (32*SB)                  // 4352
#define STAGE_E (ASZ + BSZ)          // 9472
#define GEMM_SMEM_BYTES (2*STAGE_E*2) // 37888

// flags
#define F_BIAS  1
#define F_RELU  2
#define F_GATH  4
#define F_HALF  8

struct GemmDesc {
    const h16 *A1,*B1;
    const h16 *A2,*B2;
    int K1, K2, M, N;
    const float *bias, *Demb; const int* idx;
    float* C; h16 *Ch;
    int flags;
    int start, tx;
};
struct GemmBatch { GemmDesc g[3]; int n; };

// ---------------- batched fp16 tensor-core GEMM (R13-proven, 2-stage) ----------------
__global__ __launch_bounds__(256,2) void mma_gemm_batched(GemmBatch gb)
{
    extern __shared__ h16 smem[];
    uint32_t sbase = (uint32_t)__cvta_generic_to_shared(smem);
    const int tid  = threadIdx.x;
    const int lane = tid & 31;
    const int wid  = tid >> 5;
    const int wm   = (wid & 3) * 32;
    const int wn   = (wid >> 2) * 64;

    int gi = 0;
    if (gb.n > 1 && (int)blockIdx.x >= gb.g[1].start) gi = 1;
    if (gb.n > 2 && (int)blockIdx.x >= gb.g[2].start) gi = 2;
    const GemmDesc d = gb.g[gi];

    const int rel = blockIdx.x - d.start;
    const int bn  = (rel % d.tx) * 128;
    const int bm  = (rel / d.tx) * 128;
    const int M = d.M, N = d.N;
    const int S1 = d.K1 >> 5, S2 = d.K2 >> 5, S = S1 + S2;

    float acc[2][8][4];
#pragma unroll
    for (int i=0;i<2;i++)
#pragma unroll
        for (int j=0;j<8;j++)
#pragma unroll
            for (int k=0;k<4;k++) acc[i][j][k] = 0.f;

    auto prefetch = [&](int s){
        const h16 *A,*B; int K,k0;
        if (s < S1){ A=d.A1; B=d.B1; K=d.K1; k0=s<<5; }
        else       { A=d.A2; B=d.B2; K=d.K2; k0=(s-S1)<<5; }
        uint32_t sb = sbase + (uint32_t)((s&1)*STAGE_E*2);
        int ar = tid>>2, ac = (tid&3)*8;
#pragma unroll
        for (int i=0;i<2;i++){
            int row = bm + ar + 64*i;
            bool ok = row < M;
            int sr = ok ? row : 0;
            uint32_t dd = sb + (uint32_t)(((ar+64*i)*SA + ac)*2);
            cpa16(dd, A + (size_t)sr*K + k0 + ac, ok);
        }
        int bk = tid>>4, bc = (tid&15)*8;
#pragma unroll
        for (int i=0;i<2;i++){
            int k = bk + 16*i;
            uint32_t dd = sb + (uint32_t)((ASZ + k*SB + bc)*2);
            cpa16(dd, B + (size_t)(k0 + k)*N + bn + bc, true);
        }
        asm volatile("cp.async.commit_group;");
    };

    prefetch(0);
    for (int s=0;s<S;s++){
        if (s+1 < S){
            prefetch(s+1);
            asm volatile("cp.async.wait_group 1;");
        } else {
            asm volatile("cp.async.wait_group 0;");
        }
        __syncthreads();
        uint32_t sb = sbase + (uint32_t)((s&1)*STAGE_E*2);
#pragma unroll
        for (int kk=0;kk<2;kk++){
            const int k16 = kk*16;
            const int loff = (lane>>1)&8;
            uint32_t ah[2][4];
#pragma unroll
            for (int mf=0;mf<2;mf++){
                uint32_t a = sb + (uint32_t)((((wm + mf*16 + (lane&15))*SA) + k16 + loff)*2);
                ldsm_x4(ah[mf][0],ah[mf][1],ah[mf][2],ah[mf][3], a);
            }
#pragma unroll
            for (int nb=0;nb<4;nb++){
                uint32_t a = sb + (uint32_t)((ASZ + (k16 + (lane&15))*SB + wn + nb*16 + loff)*2);
                uint32_t bh[4];
                ldsm_x4t(bh[0],bh[1],bh[2],bh[3], a);
#pragma unroll
                for (int h=0;h<2;h++){
#pragma unroll
                    for (int mf=0;mf<2;mf++){
                        mma_f16(acc[mf][nb*2+h], ah[mf], bh[2*h], bh[2*h+1]);
                    }
                }
            }
        }
        __syncthreads();
    }

    const int fl = d.flags;
#pragma unroll
    for (int mf=0;mf<2;mf++){
#pragma unroll
        for (int nf=0;nf<8;nf++){
            int col = bn + wn + nf*8 + (lane&3)*2;
#pragma unroll
            for (int half=0;half<2;half++){
                int row = bm + wm + mf*16 + (lane>>2) + half*8;
                if (row >= M) continue;
                float v0 = acc[mf][nf][half*2+0];
                float v1 = acc[mf][nf][half*2+1];
                if (fl & F_BIAS){ v0 += __ldg(&d.bias[col]); v1 += __ldg(&d.bias[col+1]); }
                if (fl & F_GATH){
                    int g = __ldg(&d.idx[row]);
                    const float* e = d.Demb + (size_t)g*N + col;
                    v0 += __ldg(&e[0]); v1 += __ldg(&e[1]);
                }
                if (fl & F_RELU){ v0 = fmaxf(v0,0.f); v1 = fmaxf(v1,0.f); }
                if (fl & F_HALF){
                    *(h162*)(d.Ch + (size_t)row*N + col) =
                        __halves2half2(__float2half_rn(v0), __float2half_rn(v1));
                } else {
                    float2 o; o.x=v0; o.y=v1;
                    *(float2*)(d.C + (size_t)row*N + col) = o;
                }
            }
        }
    }
}

// ---------------- single merged convert fp32 -> fp16 (12 segments) ----------------
struct CvtSet { const float* x[12]; h16* h[12]; int start[13]; };
__global__ void cvt_kernel(CvtSet cs)
{
    int q = blockIdx.x*blockDim.x + threadIdx.x;
    if (q >= cs.start[12]) return;
    int z = 0;
#pragma unroll
    for (int i = 1; i < 12; i++) if (q >= cs.start[i]) z = i;
    int off = q - cs.start[z];
    float4 v = ((const float4*)cs.x[z])[off];
    h162* H = (h162*)cs.h[z];
    H[2*off]   = __halves2half2(__float2half_rn(v.x), __float2half_rn(v.y));
    H[2*off+1] = __halves2half2(__float2half_rn(v.z), __float2half_rn(v.w));
}

// ---------------- CSR build ----------------
__global__ void zero_kernel(int* a, int na, int* b, int nb)
{
    int i = blockIdx.x*blockDim.x + threadIdx.x;
    if (i < na) a[i] = 0;
    if (i < nb) b[i] = 0;
}

__global__ void count_edges_kernel(const int* __restrict__ src, const int* __restrict__ dst,
                                   int* __restrict__ cm, int* __restrict__ cd, int E)
{
    int i = blockIdx.x * blockDim.x + threadIdx.x;
    if (i < E) {
        atomicAdd(&cd[dst[i]], 1);
        atomicAdd(&cm[src[i]], 1);
    }
}

__global__ void exscan2_kernel(const int* __restrict__ cnt_d, int* __restrict__ off_d, int* __restrict__ cur_d, int n_d,
                               const int* __restrict__ cnt_m, int* __restrict__ off_m, int* __restrict__ cur_m, int n_m)
{
    const int* cnt; int* off; int* cur; int n;
    if (blockIdx.x == 0){ cnt = cnt_d; off = off_d; cur = cur_d; n = n_d; }
    else               { cnt = cnt_m; off = off_m; cur = cur_m; n = n_m; }
    __shared__ int wsum[32];
    int t = threadIdx.x;
    int chunk = (n + 1023) >> 10;
    int s = t * chunk; if (s > n) s = n;
    int e = s + chunk; if (e > n) e = n;
    int sum = 0;
    for (int i = s; i < e; i++) sum += cnt[i];
    int lane = t & 31, w = t >> 5;
    int v = sum;
#pragma unroll
    for (int dd = 1; dd < 32; dd <<= 1){
        int o = __shfl_up_sync(0xFFFFFFFFu, v, dd);
        if (lane >= dd) v += o;
    }
    if (lane == 31) wsum[w] = v;
    __syncthreads();
    if (w == 0){
        int x = wsum[lane];
#pragma unroll
        for (int dd = 1; dd < 32; dd <<= 1){
            int o = __shfl_up_sync(0xFFFFFFFFu, x, dd);
            if (lane >= dd) x += o;
        }
        wsum[lane] = x;
    }
    __syncthreads();
    int run = v - sum + (w > 0 ? wsum[w-1] : 0);
    for (int i = s; i < e; i++){
        off[i] = run; cur[i] = run; run += cnt[i];
    }
    if (t == 1023) off[n] = run;
}

__global__ void fill_csr_kernel(const int* __restrict__ src, const int* __restrict__ dst,
                                int* __restrict__ cur_m, int* __restrict__ cur_d,
                                int* __restrict__ csr_src, int* __restrict__ csr_dst, int E)
{
    int i = blockIdx.x * blockDim.x + threadIdx.x;
    if (i < E) {
        int m = src[i], d = dst[i];
        int p = atomicAdd(&cur_d[d], 1);
        csr_src[p] = m;
        int q = atomicAdd(&cur_m[m], 1);
        csr_dst[q] = d;
    }
}

// ---------------- segment mean: fp16-in -> fp16-out (multi-row blocks) ----------------
template<int WIDTH>
__global__ void seg_mean_kernel(const h16* __restrict__ X,
                                const int* __restrict__ off, const int* __restrict__ nbr,
                                h16* __restrict__ C, int nrows)
{
    const int tpr = WIDTH/4;
    const int rpb = 256/tpr;
    int row = blockIdx.x*rpb + threadIdx.x/tpr;
    if (row >= nrows) return;
    int t = threadIdx.x % tpr;
    int s = off[row], e = off[row + 1];
    float a0=0.f,a1=0.f,a2=0.f,a3=0.f;
    float b0=0.f,b1=0.f,b2=0.f,b3=0.f;
    int i = s;
    for (; i + 2 <= e; i += 2){
        int n0 = __ldg(&nbr[i]);
        int n1 = __ldg(&nbr[i+1]);
        const h162* p0 = (const h162*)(X + (size_t)n0*WIDTH);
        const h162* p1 = (const h162*)(X + (size_t)n1*WIDTH);
        float2 u0 = __half22float2(__ldg(&p0[2*t]));
        float2 u1 = __half22float2(__ldg(&p0[2*t+1]));
        float2 w0 = __half22float2(__ldg(&p1[2*t]));
        float2 w1 = __half22float2(__ldg(&p1[2*t+1]));
        a0 += u0.x; a1 += u0.y; a2 += u1.x; a3 += u1.y;
        b0 += w0.x; b1 += w0.y; b2 += w1.x; b3 += w1.y;
    }
    if (i < e){
        int n0 = __ldg(&nbr[i]);
        const h162* p0 = (const h162*)(X + (size_t)n0*WIDTH);
        float2 u0 = __half22float2(__ldg(&p0[2*t]));
        float2 u1 = __half22float2(__ldg(&p0[2*t+1]));
        a0 += u0.x; a1 += u0.y; a2 += u1.x; a3 += u1.y;
    }
    a0 += b0; a1 += b1; a2 += b2; a3 += b3;
    float inv = (e > s) ? 1.0f/(float)(e - s) : 0.0f;
    a0 *= inv; a1 *= inv; a2 *= inv; a3 *= inv;
    h162* oc = (h162*)(C + (size_t)row*WIDTH);
    oc[2*t]   = __halves2half2(__float2half_rn(a0), __float2half_rn(a1));
    oc[2*t+1] = __halves2half2(__float2half_rn(a2), __float2half_rn(a3));
}

// ---------------- seg mean (fp16 msgs) + f32 base + relu -> fp16 out ----------------
template<int WIDTH>
__global__ void seg_relu_kernel(const h16* __restrict__ Q, const float* __restrict__ Base,
                                const int* __restrict__ off, const int* __restrict__ nbr,
                                h16* __restrict__ C, int nrows)
{
    const int tpr = WIDTH/4;
    const int rpb = 256/tpr;
    int row = blockIdx.x*rpb + threadIdx.x/tpr;
    if (row >= nrows) return;
    int t = threadIdx.x % tpr;
    int s = off[row], e = off[row + 1];
    float a0=0.f,a1=0.f,a2=0.f,a3=0.f;
    float b0=0.f,b1=0.f,b2=0.f,b3=0.f;
    int i = s;
    for (; i + 2 <= e; i += 2){
        int n0 = __ldg(&nbr[i]);
        int n1 = __ldg(&nbr[i+1]);
        const h162* p0 = (const h162*)(Q + (size_t)n0*WIDTH);
        const h162* p1 = (const h162*)(Q + (size_t)n1*WIDTH);
        float2 u0 = __half22float2(__ldg(&p0[2*t]));
        float2 u1 = __half22float2(__ldg(&p0[2*t+1]));
        float2 w0 = __half22float2(__ldg(&p1[2*t]));
        float2 w1 = __half22float2(__ldg(&p1[2*t+1]));
        a0 += u0.x; a1 += u0.y; a2 += u1.x; a3 += u1.y;
        b0 += w0.x; b1 += w0.y; b2 += w1.x; b3 += w1.y;
    }
    if (i < e){
        int n0 = __ldg(&nbr[i]);
        const h162* p0 = (const h162*)(Q + (size_t)n0*WIDTH);
        float2 u0 = __half22float2(__ldg(&p0[2*t]));
        float2 u1 = __half22float2(__ldg(&p0[2*t+1]));
        a0 += u0.x; a1 += u0.y; a2 += u1.x; a3 += u1.y;
    }
    a0 += b0; a1 += b1; a2 += b2; a3 += b3;
    float inv = (e > s) ? 1.0f/(float)(e - s) : 0.0f;
    float4 bb = __ldg((const float4*)(Base + (size_t)row*WIDTH) + t);
    float x0 = fmaxf(bb.x + a0*inv, 0.f);
    float x1 = fmaxf(bb.y + a1*inv, 0.f);
    float x2 = fmaxf(bb.z + a2*inv, 0.f);
    float x3 = fmaxf(bb.w + a3*inv, 0.f);
    h162* oc = (h162*)(C + (size_t)row*WIDTH);
    oc[2*t]   = __halves2half2(__float2half_rn(x0), __float2half_rn(x1));
    oc[2*t+1] = __halves2half2(__float2half_rn(x2), __float2half_rn(x3));
}

// ---------------- seg mean: fp16-in, accumulate into f32 out ----------------
template <int WIDTH>
__global__ void seg_mean_acc_kernel(const h16* __restrict__ X, const int* __restrict__ off,
                                    const int* __restrict__ nbr, float* __restrict__ C, int nrows)
{
    const int tpr = WIDTH/4;
    const int rpb = 256/tpr;
    int row = blockIdx.x*rpb + threadIdx.x/tpr;
    if (row >= nrows) return;
    int t = threadIdx.x % tpr;
    int s = off[row], e = off[row + 1];
    float a0=0.f,a1=0.f,a2=0.f,a3=0.f;
    float b0=0.f,b1=0.f,b2=0.f,b3=0.f;
    int i = s;
    for (; i + 2 <= e; i += 2){
        int n0 = __ldg(&nbr[i]);
        int n1 = __ldg(&nbr[i+1]);
        const h162* p0 = (const h162*)(X + (size_t)n0*WIDTH);
        const h162* p1 = (const h162*)(X + (size_t)n1*WIDTH);
        float2 u0 = __half22float2(__ldg(&p0[2*t]));
        float2 u1 = __half22float2(__ldg(&p0[2*t+1]));
        float2 w0 = __half22float2(__ldg(&p1[2*t]));
        float2 w1 = __half22float2(__ldg(&p1[2*t+1]));
        a0 += u0.x; a1 += u0.y; a2 += u1.x; a3 += u1.y;
        b0 += w0.x; b1 += w0.y; b2 += w1.x; b3 += w1.y;
    }
    if (i < e){
        int n0 = __ldg(&nbr[i]);
        const h162* p0 = (const h162*)(X + (size_t)n0*WIDTH);
        float2 u0 = __half22float2(__ldg(&p0[2*t]));
        float2 u1 = __half22float2(__ldg(&p0[2*t+1]));
        a0 += u0.x; a1 += u0.y; a2 += u1.x; a3 += u1.y;
    }
    a0 += b0; a1 += b1; a2 += b2; a3 += b3;
    float inv = (e > s) ? 1.0f / (float)(e - s) : 0.0f;
    float4* cp = (float4*)(C + (size_t)row * WIDTH) + t;
    float4 o = *cp;
    o.x += a0*inv; o.y += a1*inv; o.z += a2*inv; o.w += a3*inv;
    *cp = o;
}

// ---------------- host orchestration ----------------
#define SYM(p, s) cudaGetSymbolAddress((void**)&(p), s)

static inline GemmDesc mk_desc(
    const h16* A1, const h16* B1, int K1,
    const h16* A2, const h16* B2, int K2,
    int M, int N, const float* bias, const float* Demb, const int* idx,
    float* C, h16* Ch, int flags)
{
    GemmDesc d;
    d.A1=A1; d.B1=B1; d.K1=K1;
    d.A2=A2; d.B2=B2; d.K2=K2;
    d.M=M; d.N=N; d.bias=bias; d.Demb=Demb; d.idx=idx;
    d.C=C; d.Ch=Ch; d.flags=flags;
    d.start=0; d.tx=N/128;
    return d;
}

static inline void launch_batch(GemmDesc* descs, int n, cudaStream_t st)
{
    GemmBatch gb;
    int total = 0;
    for (int i = 0; i < n; i++){
        descs[i].start = total;
        total += descs[i].tx * ((descs[i].M + 127)/128);
        gb.g[i] = descs[i];
    }
    for (int i = n; i < 3; i++){ gb.g[i] = descs[n-1]; gb.g[i].start = 0x7FFFFFFF; }
    gb.n = n;
    mma_gemm_batched<<<total, 256, GEMM_SMEM_BYTES, st>>>(gb);
}

// static aux resources (created on first, uncaptured, call)
struct Aux {
    cudaStream_t s2;
    cudaEvent_t ev[4];
    Aux(){
        cudaStreamCreateWithFlags(&s2, cudaStreamNonBlocking);
        for (int i = 0; i < 4; i++)
            cudaEventCreateWithFlags(&ev[i], cudaEventDisableTiming);
    }
};

extern "C" void kernel_launch(void* const* d_in, const int* in_sizes, int n_in,
                              void* d_out, int out_size)
{
    static Aux aux;

    cudaStream_t ms = cudaStreamPerThread;
    {
        cudaStreamCaptureStatus st = cudaStreamCaptureStatusNone;
        if (cudaStreamIsCapturing(cudaStreamPerThread, &st) == cudaSuccess &&
            st == cudaStreamCaptureStatusActive) {
            ms = cudaStreamPerThread;
        } else {
            cudaGetLastError();
            st = cudaStreamCaptureStatusNone;
            if (cudaStreamIsCapturing(cudaStreamLegacy, &st) == cudaSuccess &&
                st == cudaStreamCaptureStatusActive) {
                ms = cudaStreamLegacy;
            }
            cudaGetLastError();
        }
    }
    cudaStream_t s2 = aux.s2;

    const float* mf   = (const float*)d_in[0];
    const float* df   = (const float*)d_in[1];
    const int*   mid  = (const int*)d_in[2];
    const int*   did  = (const int*)d_in[3];
    const int*   esrc = (const int*)d_in[4];
    const int*   edst = (const int*)d_in[5];
    const float* Wm   = (const float*)d_in[6];
    const float* bm   = (const float*)d_in[7];
    const float* Wd   = (const float*)d_in[8];
    const float* bd   = (const float*)d_in[9];
    const float* memb = (const float*)d_in[10];
    const float* demb = (const float*)d_in[11];
    const float* W1mdl = (const float*)d_in[12];
    const float* b1md  = (const float*)d_in[13];
    const float* W1mdr = (const float*)d_in[14];
    const float* W1dml = (const float*)d_in[15];
    const float* b1dm  = (const float*)d_in[16];
    const float* W1dmr = (const float*)d_in[17];
    const float* W2mdl = (const float*)d_in[18];
    const float* b2md  = (const float*)d_in[19];
    const float* W2mdr = (const float*)d_in[20];
    const float* W2dml = (const float*)d_in[21];
    const float* b2dm  = (const float*)d_in[22];
    const float* W2dmr = (const float*)d_in[23];

    float* out = (float*)d_out;
    float* o_m = out;
    float* o_d = out + (size_t)NM * OD;

    h16 *mfh,*dfh,*xm,*xd,*ad,*ad2,*hm,*hd,*qd,*ud;
    h16 *wm,*wd,*w1mdl,*w1mdr,*w1dml,*w1dmr,*w2mdl,*w2mdr,*w2dml,*w2dmr;
    float *basem;
    int *cnt_m,*cnt_d,*off_m,*off_d,*cur_m,*cur_d,*csr_src,*csr_dst;
    SYM(mfh,g_mf); SYM(dfh,g_df);
    SYM(xm,g_xm); SYM(xd,g_xd);
    SYM(ad,g_ad); SYM(ad2,g_ad2);
    SYM(hm,g_hm); SYM(hd,g_hd);
    SYM(qd,g_qd); SYM(ud,g_ud);
    SYM(wm,g_wm); SYM(wd,g_wd);
    SYM(w1mdl,g_w1mdl); SYM(w1mdr,g_w1mdr); SYM(w1dml,g_w1dml); SYM(w1dmr,g_w1dmr);
    SYM(w2mdl,g_w2mdl); SYM(w2mdr,g_w2mdr); SYM(w2dml,g_w2dml); SYM(w2dmr,g_w2dmr);
    SYM(basem,g_base);
    SYM(cnt_m,g_cnt_m); SYM(cnt_d,g_cnt_d); SYM(off_m,g_off_m); SYM(off_d,g_off_d);
    SYM(cur_m,g_cur_m); SYM(cur_d,g_cur_d); SYM(csr_src,g_csr_src); SYM(csr_dst,g_csr_dst);

    cudaFuncSetAttribute(mma_gemm_batched, cudaFuncAttributeMaxDynamicSharedMemorySize, GEMM_SMEM_BYTES);

    // ---- fork s2: CSR chain overlaps with converts+encoders ----
    cudaEventRecord(aux.ev[0], ms);
    cudaStreamWaitEvent(s2, aux.ev[0], 0);
    zero_kernel<<<(NM + 255)/256, 256, 0, s2>>>(cnt_m, NM, cnt_d, ND);
    count_edges_kernel<<<(NE + 255) / 256, 256, 0, s2>>>(esrc, edst, cnt_m, cnt_d, NE);
    exscan2_kernel<<<2, 1024, 0, s2>>>(cnt_d, off_d, cur_d, ND, cnt_m, off_m, cur_m, NM);
    fill_csr_kernel<<<(NE + 255) / 256, 256, 0, s2>>>(esrc, edst, cur_m, cur_d, csr_src, csr_dst, NE);
    cudaEventRecord(aux.ev[1], s2);   // CSR ready

    // ---- main: one merged convert launch ----
    {
        CvtSet cs;
        const float* xs[12] = {mf, df, Wm, Wd, W1mdl, W1mdr, W1dml, W1dmr,
                               W2mdl, W2mdr, W2dml, W2dmr};
        h16* hs[12] = {mfh, dfh, wm, wd, w1mdl, w1mdr, w1dml, w1dmr,
                       w2mdl, w2mdr, w2dml, w2dmr};
        int n4s[12] = {NM*FIN/4, ND*FIN/4, FIN*HD/4, FIN*HD/4,
                       HD*H1/4, HD*H1/4, HD*H1/4, HD*H1/4,
                       H1*OD/4, H1*OD/4, H1*OD/4, H1*OD/4};
        int run = 0;
        for (int i = 0; i < 12; i++){
            cs.x[i] = xs[i]; cs.h[i] = hs[i]; cs.start[i] = run; run += n4s[i];
        }
        cs.start[12] = run;
        cvt_kernel<<<(run + 255)/256, 256, 0, ms>>>(cs);
    }

    // ---- main: L1 encoders ----
    {
        GemmDesc ds[2] = {
            mk_desc(mfh, wm, FIN, 0,0, 0,
                    NM, HD, bm, memb, mid, nullptr, xm, F_BIAS|F_GATH|F_HALF),
            mk_desc(dfh, wd, FIN, 0,0, 0,
                    ND, HD, bd, demb, did, nullptr, xd, F_BIAS|F_GATH|F_HALF)
        };
        launch_batch(ds, 2, ms);
    }

    // join: CSR ready before first gather
    cudaStreamWaitEvent(ms, aux.ev[1], 0);

    // ---- main: layer1 md aggregation ----
    {
        const int rpb = 256/(HD/4);
        seg_mean_kernel<HD><<<(ND + rpb - 1)/rpb, 256, 0, ms>>>(xm, off_d, csr_src, ad, ND);
    }

    // ---- main: Group B: L1md-dual + qd + base_m ----
    {
        GemmDesc ds[3] = {
            mk_desc(ad, w1mdl, HD, xd, w1mdr, HD,
                    ND, H1, b1md, nullptr, nullptr, nullptr, hd, F_BIAS|F_RELU|F_HALF),
            mk_desc(xd, w1dml, HD, 0,0, 0,
                    ND, H1, nullptr, nullptr, nullptr, nullptr, qd, F_HALF),
            mk_desc(xm, w1dmr, HD, 0,0, 0,
                    NM, H1, b1dm, nullptr, nullptr, basem, nullptr, F_BIAS)
        };
        launch_batch(ds, 3, ms);
    }

    // ---- main: h_m = relu(base + mean(q_d)); layer2 md aggregation ----
    {
        const int rpb = 256/(H1/4);
        seg_relu_kernel<H1><<<(NM + rpb - 1)/rpb, 256, 0, ms>>>(qd, basem, off_m, csr_dst, hm, NM);
        seg_mean_kernel<H1><<<(ND + rpb - 1)/rpb, 256, 0, ms>>>(hm, off_d, csr_src, ad2, ND);
    }

    // ---- main: Group C: L2md-dual + ud + o_m base ----
    {
        GemmDesc ds[3] = {
            mk_desc(ad2, w2mdl, H1, hd, w2mdr, H1,
                    ND, OD, b2md, nullptr, nullptr, o_d, nullptr, F_BIAS),
            mk_desc(hd, w2dml, H1, 0,0, 0,
                    ND, OD, nullptr, nullptr, nullptr, nullptr, ud, F_HALF),
            mk_desc(hm, w2dmr, H1, 0,0, 0,
                    NM, OD, b2dm, nullptr, nullptr, o_m, nullptr, F_BIAS)
        };
        launch_batch(ds, 3, ms);
    }

    // ---- main: o_m += mean(ud over incident diseases) ----
    {
        const int rpb = 256/(OD/4);
        seg_mean_acc_kernel<OD><<<(NM + rpb - 1)/rpb, 256, 0, ms>>>(ud, off_m, csr_dst, o_m, NM);
    }
}

// round 16
// speedup vs baseline: 1.0303x; 1.0303x over previous
#include <cuda_runtime.h>
#include <cuda_fp16.h>
#include <cstdint>

#define NM 20000
#define ND 8000
#define NE 200000
#define FIN 384
#define HD 512
#define H1 512
#define OD 256

typedef __half  h16;
typedef __half2 h162;

// ---------------- scratch (device globals) ----------------
__device__ h16 g_mf[NM*FIN];
__device__ h16 g_df[ND*FIN];
__device__ h16 g_xm[NM*HD];
__device__ h16 g_xd[ND*HD];
__device__ h16 g_ad[ND*HD];
__device__ h16 g_ad2[ND*H1];
__device__ h16 g_hm[NM*H1];
__device__ h16 g_hd[ND*H1];
__device__ h16 g_qd[ND*H1];
__device__ h16 g_base[NM*H1];   // layer1 dm base, fp16 (h_m is fp16-rounded anyway)
__device__ h16 g_ud[ND*OD];
__device__ h16 g_wm[FIN*HD], g_wd[FIN*HD];
__device__ h16 g_w1mdl[HD*H1], g_w1mdr[HD*H1];
__device__ h16 g_w1dml[HD*H1], g_w1dmr[HD*H1];
__device__ h16 g_w2mdl[H1*OD], g_w2mdr[H1*OD];
__device__ h16 g_w2dml[H1*OD], g_w2dmr[H1*OD];
__device__ int g_cnt_m[NM], g_cnt_d[ND];
__device__ int g_off_m[NM+1], g_off_d[ND+1];
__device__ int g_cur_m[NM], g_cur_d[ND];
__device__ int g_csr_src[NE];
__device__ int g_csr_dst[NE];

// ---------------- PTX helpers ----------------
__device__ __forceinline__ void ldsm_x4(uint32_t& r0,uint32_t& r1,uint32_t& r2,uint32_t& r3,uint32_t a){
    asm volatile("ldmatrix.sync.aligned.m8n8.x4.shared.b16 {%0,%1,%2,%3},[%4];"
                 :"=r"(r0),"=r"(r1),"=r"(r2),"=r"(r3):"r"(a));
}
__device__ __forceinline__ void ldsm_x4t(uint32_t& r0,uint32_t& r1,uint32_t& r2,uint32_t& r3,uint32_t a){
    asm volatile("ldmatrix.sync.aligned.m8n8.x4.trans.shared.b16 {%0,%1,%2,%3},[%4];"
                 :"=r"(r0),"=r"(r1),"=r"(r2),"=r"(r3):"r"(a));
}
__device__ __forceinline__ void mma_f16(float* c, const uint32_t* a, uint32_t b0, uint32_t b1){
    asm volatile("mma.sync.aligned.m16n8k16.row.col.f32.f16.f16.f32 "
        "{%0,%1,%2,%3},{%4,%5,%6,%7},{%8,%9},{%0,%1,%2,%3};"
        :"+f"(c[0]),"+f"(c[1]),"+f"(c[2]),"+f"(c[3])
        :"r"(a[0]),"r"(a[1]),"r"(a[2]),"r"(a[3]),"r"(b0),"r"(b1));
}
__device__ __forceinline__ void cpa16(uint32_t d, const void* s, bool p){
    int sz = p ? 16 : 0;
    asm volatile("cp.async.cg.shared.global [%0],[%1],16,%2;"::"r"(d),"l"(s),"r"(sz));
}

// smem geometry (fp16 elements); 2-stage pipeline (R13-proven)
#define SA 40
#define SB 136
#define ASZ (128*SA)                 // 5120
#define BSZ (32*SB)                  // 4352
#define STAGE_E (ASZ + BSZ)          // 9472
#define GEMM_SMEM_BYTES (2*STAGE_E*2) // 37888

// flags
#define F_BIAS  1
#define F_RELU  2
#define F_GATH  4
#define F_HALF  8

struct GemmDesc {
    const h16 *A1,*B1;
    const h16 *A2,*B2;
    int K1, K2, M, N;
    const float *bias, *Demb; const int* idx;
    float* C; h16 *Ch;
    int flags;
    int start, tx;
};
struct GemmBatch { GemmDesc g[3]; int n; };

// ---------------- batched fp16 tensor-core GEMM (R13-proven, 2-stage) ----------------
__global__ __launch_bounds__(256,2) void mma_gemm_batched(GemmBatch gb)
{
    extern __shared__ h16 smem[];
    uint32_t sbase = (uint32_t)__cvta_generic_to_shared(smem);
    const int tid  = threadIdx.x;
    const int lane = tid & 31;
    const int wid  = tid >> 5;
    const int wm   = (wid & 3) * 32;
    const int wn   = (wid >> 2) * 64;

    int gi = 0;
    if (gb.n > 1 && (int)blockIdx.x >= gb.g[1].start) gi = 1;
    if (gb.n > 2 && (int)blockIdx.x >= gb.g[2].start) gi = 2;
    const GemmDesc d = gb.g[gi];

    const int rel = blockIdx.x - d.start;
    const int bn  = (rel % d.tx) * 128;
    const int bm  = (rel / d.tx) * 128;
    const int M = d.M, N = d.N;
    const int S1 = d.K1 >> 5, S2 = d.K2 >> 5, S = S1 + S2;

    float acc[2][8][4];
#pragma unroll
    for (int i=0;i<2;i++)
#pragma unroll
        for (int j=0;j<8;j++)
#pragma unroll
            for (int k=0;k<4;k++) acc[i][j][k] = 0.f;

    auto prefetch = [&](int s){
        const h16 *A,*B; int K,k0;
        if (s < S1){ A=d.A1; B=d.B1; K=d.K1; k0=s<<5; }
        else       { A=d.A2; B=d.B2; K=d.K2; k0=(s-S1)<<5; }
        uint32_t sb = sbase + (uint32_t)((s&1)*STAGE_E*2);
        int ar = tid>>2, ac = (tid&3)*8;
#pragma unroll
        for (int i=0;i<2;i++){
            int row = bm + ar + 64*i;
            bool ok = row < M;
            int sr = ok ? row : 0;
            uint32_t dd = sb + (uint32_t)(((ar+64*i)*SA + ac)*2);
            cpa16(dd, A + (size_t)sr*K + k0 + ac, ok);
        }
        int bk = tid>>4, bc = (tid&15)*8;
#pragma unroll
        for (int i=0;i<2;i++){
            int k = bk + 16*i;
            uint32_t dd = sb + (uint32_t)((ASZ + k*SB + bc)*2);
            cpa16(dd, B + (size_t)(k0 + k)*N + bn + bc, true);
        }
        asm volatile("cp.async.commit_group;");
    };

    prefetch(0);
    for (int s=0;s<S;s++){
        if (s+1 < S){
            prefetch(s+1);
            asm volatile("cp.async.wait_group 1;");
        } else {
            asm volatile("cp.async.wait_group 0;");
        }
        __syncthreads();
        uint32_t sb = sbase + (uint32_t)((s&1)*STAGE_E*2);
#pragma unroll
        for (int kk=0;kk<2;kk++){
            const int k16 = kk*16;
            const int loff = (lane>>1)&8;
            uint32_t ah[2][4];
#pragma unroll
            for (int mf=0;mf<2;mf++){
                uint32_t a = sb + (uint32_t)((((wm + mf*16 + (lane&15))*SA) + k16 + loff)*2);
                ldsm_x4(ah[mf][0],ah[mf][1],ah[mf][2],ah[mf][3], a);
            }
#pragma unroll
            for (int nb=0;nb<4;nb++){
                uint32_t a = sb + (uint32_t)((ASZ + (k16 + (lane&15))*SB + wn + nb*16 + loff)*2);
                uint32_t bh[4];
                ldsm_x4t(bh[0],bh[1],bh[2],bh[3], a);
#pragma unroll
                for (int h=0;h<2;h++){
#pragma unroll
                    for (int mf=0;mf<2;mf++){
                        mma_f16(acc[mf][nb*2+h], ah[mf], bh[2*h], bh[2*h+1]);
                    }
                }
            }
        }
        __syncthreads();
    }

    const int fl = d.flags;
#pragma unroll
    for (int mf=0;mf<2;mf++){
#pragma unroll
        for (int nf=0;nf<8;nf++){
            int col = bn + wn + nf*8 + (lane&3)*2;
#pragma unroll
            for (int half=0;half<2;half++){
                int row = bm + wm + mf*16 + (lane>>2) + half*8;
                if (row >= M) continue;
                float v0 = acc[mf][nf][half*2+0];
                float v1 = acc[mf][nf][half*2+1];
                if (fl & F_BIAS){ v0 += __ldg(&d.bias[col]); v1 += __ldg(&d.bias[col+1]); }
                if (fl & F_GATH){
                    int g = __ldg(&d.idx[row]);
                    const float* e = d.Demb + (size_t)g*N + col;
                    v0 += __ldg(&e[0]); v1 += __ldg(&e[1]);
                }
                if (fl & F_RELU){ v0 = fmaxf(v0,0.f); v1 = fmaxf(v1,0.f); }
                if (fl & F_HALF){
                    *(h162*)(d.Ch + (size_t)row*N + col) =
                        __halves2half2(__float2half_rn(v0), __float2half_rn(v1));
                } else {
                    float2 o; o.x=v0; o.y=v1;
                    *(float2*)(d.C + (size_t)row*N + col) = o;
                }
            }
        }
    }
}

// ---------------- single merged convert fp32 -> fp16 (12 segments) ----------------
struct CvtSet { const float* x[12]; h16* h[12]; int start[13]; };
__global__ void cvt_kernel(CvtSet cs)
{
    int q = blockIdx.x*blockDim.x + threadIdx.x;
    if (q >= cs.start[12]) return;
    int z = 0;
#pragma unroll
    for (int i = 1; i < 12; i++) if (q >= cs.start[i]) z = i;
    int off = q - cs.start[z];
    float4 v = ((const float4*)cs.x[z])[off];
    h162* H = (h162*)cs.h[z];
    H[2*off]   = __halves2half2(__float2half_rn(v.x), __float2half_rn(v.y));
    H[2*off+1] = __halves2half2(__float2half_rn(v.z), __float2half_rn(v.w));
}

// ---------------- CSR build ----------------
__global__ void zero_kernel(int* a, int na, int* b, int nb)
{
    int i = blockIdx.x*blockDim.x + threadIdx.x;
    if (i < na) a[i] = 0;
    if (i < nb) b[i] = 0;
}

__global__ void count_edges_kernel(const int* __restrict__ src, const int* __restrict__ dst,
                                   int* __restrict__ cm, int* __restrict__ cd, int E)
{
    int i = blockIdx.x * blockDim.x + threadIdx.x;
    if (i < E) {
        atomicAdd(&cd[dst[i]], 1);
        atomicAdd(&cm[src[i]], 1);
    }
}

__global__ void exscan2_kernel(const int* __restrict__ cnt_d, int* __restrict__ off_d, int* __restrict__ cur_d, int n_d,
                               const int* __restrict__ cnt_m, int* __restrict__ off_m, int* __restrict__ cur_m, int n_m)
{
    const int* cnt; int* off; int* cur; int n;
    if (blockIdx.x == 0){ cnt = cnt_d; off = off_d; cur = cur_d; n = n_d; }
    else               { cnt = cnt_m; off = off_m; cur = cur_m; n = n_m; }
    __shared__ int wsum[32];
    int t = threadIdx.x;
    int chunk = (n + 1023) >> 10;
    int s = t * chunk; if (s > n) s = n;
    int e = s + chunk; if (e > n) e = n;
    int sum = 0;
    for (int i = s; i < e; i++) sum += cnt[i];
    int lane = t & 31, w = t >> 5;
    int v = sum;
#pragma unroll
    for (int dd = 1; dd < 32; dd <<= 1){
        int o = __shfl_up_sync(0xFFFFFFFFu, v, dd);
        if (lane >= dd) v += o;
    }
    if (lane == 31) wsum[w] = v;
    __syncthreads();
    if (w == 0){
        int x = wsum[lane];
#pragma unroll
        for (int dd = 1; dd < 32; dd <<= 1){
            int o = __shfl_up_sync(0xFFFFFFFFu, x, dd);
            if (lane >= dd) x += o;
        }
        wsum[lane] = x;
    }
    __syncthreads();
    int run = v - sum + (w > 0 ? wsum[w-1] : 0);
    for (int i = s; i < e; i++){
        off[i] = run; cur[i] = run; run += cnt[i];
    }
    if (t == 1023) off[n] = run;
}

__global__ void fill_csr_kernel(const int* __restrict__ src, const int* __restrict__ dst,
                                int* __restrict__ cur_m, int* __restrict__ cur_d,
                                int* __restrict__ csr_src, int* __restrict__ csr_dst, int E)
{
    int i = blockIdx.x * blockDim.x + threadIdx.x;
    if (i < E) {
        int m = src[i], d = dst[i];
        int p = atomicAdd(&cur_d[d], 1);
        csr_src[p] = m;
        int q = atomicAdd(&cur_m[m], 1);
        csr_dst[q] = d;
    }
}

// ---------------- segment mean: fp16-in -> fp16-out (R13: one row per block) ----------------
template<int WIDTH>
__global__ void seg_mean_kernel(const h16* __restrict__ X,
                                const int* __restrict__ off, const int* __restrict__ nbr,
                                h16* __restrict__ C)
{
    int row = blockIdx.x;
    int t = threadIdx.x;
    int s = off[row], e = off[row + 1];
    float a0=0.f,a1=0.f,a2=0.f,a3=0.f;
    float b0=0.f,b1=0.f,b2=0.f,b3=0.f;
    int i = s;
    for (; i + 2 <= e; i += 2){
        int n0 = __ldg(&nbr[i]);
        int n1 = __ldg(&nbr[i+1]);
        const h162* p0 = (const h162*)(X + (size_t)n0*WIDTH);
        const h162* p1 = (const h162*)(X + (size_t)n1*WIDTH);
        float2 u0 = __half22float2(__ldg(&p0[2*t]));
        float2 u1 = __half22float2(__ldg(&p0[2*t+1]));
        float2 w0 = __half22float2(__ldg(&p1[2*t]));
        float2 w1 = __half22float2(__ldg(&p1[2*t+1]));
        a0 += u0.x; a1 += u0.y; a2 += u1.x; a3 += u1.y;
        b0 += w0.x; b1 += w0.y; b2 += w1.x; b3 += w1.y;
    }
    if (i < e){
        int n0 = __ldg(&nbr[i]);
        const h162* p0 = (const h162*)(X + (size_t)n0*WIDTH);
        float2 u0 = __half22float2(__ldg(&p0[2*t]));
        float2 u1 = __half22float2(__ldg(&p0[2*t+1]));
        a0 += u0.x; a1 += u0.y; a2 += u1.x; a3 += u1.y;
    }
    a0 += b0; a1 += b1; a2 += b2; a3 += b3;
    float inv = (e > s) ? 1.0f/(float)(e - s) : 0.0f;
    a0 *= inv; a1 *= inv; a2 *= inv; a3 *= inv;
    h162* oc = (h162*)(C + (size_t)row*WIDTH);
    oc[2*t]   = __halves2half2(__float2half_rn(a0), __float2half_rn(a1));
    oc[2*t+1] = __halves2half2(__float2half_rn(a2), __float2half_rn(a3));
}

// ---------------- seg mean (fp16 msgs) + fp16 base + relu -> fp16 out ----------------
template<int WIDTH>
__global__ void seg_relu_kernel(const h16* __restrict__ Q, const h16* __restrict__ Base,
                                const int* __restrict__ off, const int* __restrict__ nbr,
                                h16* __restrict__ C)
{
    int row = blockIdx.x;
    int t = threadIdx.x;
    int s = off[row], e = off[row + 1];
    float a0=0.f,a1=0.f,a2=0.f,a3=0.f;
    float b0=0.f,b1=0.f,b2=0.f,b3=0.f;
    int i = s;
    for (; i + 2 <= e; i += 2){
        int n0 = __ldg(&nbr[i]);
        int n1 = __ldg(&nbr[i+1]);
        const h162* p0 = (const h162*)(Q + (size_t)n0*WIDTH);
        const h162* p1 = (const h162*)(Q + (size_t)n1*WIDTH);
        float2 u0 = __half22float2(__ldg(&p0[2*t]));
        float2 u1 = __half22float2(__ldg(&p0[2*t+1]));
        float2 w0 = __half22float2(__ldg(&p1[2*t]));
        float2 w1 = __half22float2(__ldg(&p1[2*t+1]));
        a0 += u0.x; a1 += u0.y; a2 += u1.x; a3 += u1.y;
        b0 += w0.x; b1 += w0.y; b2 += w1.x; b3 += w1.y;
    }
    if (i < e){
        int n0 = __ldg(&nbr[i]);
        const h162* p0 = (const h162*)(Q + (size_t)n0*WIDTH);
        float2 u0 = __half22float2(__ldg(&p0[2*t]));
        float2 u1 = __half22float2(__ldg(&p0[2*t+1]));
        a0 += u0.x; a1 += u0.y; a2 += u1.x; a3 += u1.y;
    }
    a0 += b0; a1 += b1; a2 += b2; a3 += b3;
    float inv = (e > s) ? 1.0f/(float)(e - s) : 0.0f;
    const h162* bp = (const h162*)(Base + (size_t)row*WIDTH);
    float2 bb0 = __half22float2(__ldg(&bp[2*t]));
    float2 bb1 = __half22float2(__ldg(&bp[2*t+1]));
    float x0 = fmaxf(bb0.x + a0*inv, 0.f);
    float x1 = fmaxf(bb0.y + a1*inv, 0.f);
    float x2 = fmaxf(bb1.x + a2*inv, 0.f);
    float x3 = fmaxf(bb1.y + a3*inv, 0.f);
    h162* oc = (h162*)(C + (size_t)row*WIDTH);
    oc[2*t]   = __halves2half2(__float2half_rn(x0), __float2half_rn(x1));
    oc[2*t+1] = __halves2half2(__float2half_rn(x2), __float2half_rn(x3));
}

// ---------------- seg mean: fp16-in, accumulate into f32 out ----------------
template <int WIDTH>
__global__ void seg_mean_acc_kernel(const h16* __restrict__ X, const int* __restrict__ off,
                                    const int* __restrict__ nbr, float* __restrict__ C)
{
    int row = blockIdx.x;
    int t = threadIdx.x;
    int s = off[row], e = off[row + 1];
    float a0=0.f,a1=0.f,a2=0.f,a3=0.f;
    float b0=0.f,b1=0.f,b2=0.f,b3=0.f;
    int i = s;
    for (; i + 2 <= e; i += 2){
        int n0 = __ldg(&nbr[i]);
        int n1 = __ldg(&nbr[i+1]);
        const h162* p0 = (const h162*)(X + (size_t)n0*WIDTH);
        const h162* p1 = (const h162*)(X + (size_t)n1*WIDTH);
        float2 u0 = __half22float2(__ldg(&p0[2*t]));
        float2 u1 = __half22float2(__ldg(&p0[2*t+1]));
        float2 w0 = __half22float2(__ldg(&p1[2*t]));
        float2 w1 = __half22float2(__ldg(&p1[2*t+1]));
        a0 += u0.x; a1 += u0.y; a2 += u1.x; a3 += u1.y;
        b0 += w0.x; b1 += w0.y; b2 += w1.x; b3 += w1.y;
    }
    if (i < e){
        int n0 = __ldg(&nbr[i]);
        const h162* p0 = (const h162*)(X + (size_t)n0*WIDTH);
        float2 u0 = __half22float2(__ldg(&p0[2*t]));
        float2 u1 = __half22float2(__ldg(&p0[2*t+1]));
        a0 += u0.x; a1 += u0.y; a2 += u1.x; a3 += u1.y;
    }
    a0 += b0; a1 += b1; a2 += b2; a3 += b3;
    float inv = (e > s) ? 1.0f / (float)(e - s) : 0.0f;
    float4* cp = (float4*)(C + (size_t)row * WIDTH) + t;
    float4 o = *cp;
    o.x += a0*inv; o.y += a1*inv; o.z += a2*inv; o.w += a3*inv;
    *cp = o;
}

// ---------------- host orchestration ----------------
#define SYM(p, s) cudaGetSymbolAddress((void**)&(p), s)

static inline GemmDesc mk_desc(
    const h16* A1, const h16* B1, int K1,
    const h16* A2, const h16* B2, int K2,
    int M, int N, const float* bias, const float* Demb, const int* idx,
    float* C, h16* Ch, int flags)
{
    GemmDesc d;
    d.A1=A1; d.B1=B1; d.K1=K1;
    d.A2=A2; d.B2=B2; d.K2=K2;
    d.M=M; d.N=N; d.bias=bias; d.Demb=Demb; d.idx=idx;
    d.C=C; d.Ch=Ch; d.flags=flags;
    d.start=0; d.tx=N/128;
    return d;
}

static inline void launch_batch(GemmDesc* descs, int n, cudaStream_t st)
{
    GemmBatch gb;
    int total = 0;
    for (int i = 0; i < n; i++){
        descs[i].start = total;
        total += descs[i].tx * ((descs[i].M + 127)/128);
        gb.g[i] = descs[i];
    }
    for (int i = n; i < 3; i++){ gb.g[i] = descs[n-1]; gb.g[i].start = 0x7FFFFFFF; }
    gb.n = n;
    mma_gemm_batched<<<total, 256, GEMM_SMEM_BYTES, st>>>(gb);
}

// static aux resources (created on first, uncaptured, call)
struct Aux {
    cudaStream_t s2;
    cudaEvent_t ev[4];
    Aux(){
        cudaStreamCreateWithFlags(&s2, cudaStreamNonBlocking);
        for (int i = 0; i < 4; i++)
            cudaEventCreateWithFlags(&ev[i], cudaEventDisableTiming);
    }
};

extern "C" void kernel_launch(void* const* d_in, const int* in_sizes, int n_in,
                              void* d_out, int out_size)
{
    static Aux aux;

    cudaStream_t ms = cudaStreamPerThread;
    {
        cudaStreamCaptureStatus st = cudaStreamCaptureStatusNone;
        if (cudaStreamIsCapturing(cudaStreamPerThread, &st) == cudaSuccess &&
            st == cudaStreamCaptureStatusActive) {
            ms = cudaStreamPerThread;
        } else {
            cudaGetLastError();
            st = cudaStreamCaptureStatusNone;
            if (cudaStreamIsCapturing(cudaStreamLegacy, &st) == cudaSuccess &&
                st == cudaStreamCaptureStatusActive) {
                ms = cudaStreamLegacy;
            }
            cudaGetLastError();
        }
    }
    cudaStream_t s2 = aux.s2;

    const float* mf   = (const float*)d_in[0];
    const float* df   = (const float*)d_in[1];
    const int*   mid  = (const int*)d_in[2];
    const int*   did  = (const int*)d_in[3];
    const int*   esrc = (const int*)d_in[4];
    const int*   edst = (const int*)d_in[5];
    const float* Wm   = (const float*)d_in[6];
    const float* bm   = (const float*)d_in[7];
    const float* Wd   = (const float*)d_in[8];
    const float* bd   = (const float*)d_in[9];
    const float* memb = (const float*)d_in[10];
    const float* demb = (const float*)d_in[11];
    const float* W1mdl = (const float*)d_in[12];
    const float* b1md  = (const float*)d_in[13];
    const float* W1mdr = (const float*)d_in[14];
    const float* W1dml = (const float*)d_in[15];
    const float* b1dm  = (const float*)d_in[16];
    const float* W1dmr = (const float*)d_in[17];
    const float* W2mdl = (const float*)d_in[18];
    const float* b2md  = (const float*)d_in[19];
    const float* W2mdr = (const float*)d_in[20];
    const float* W2dml = (const float*)d_in[21];
    const float* b2dm  = (const float*)d_in[22];
    const float* W2dmr = (const float*)d_in[23];

    float* out = (float*)d_out;
    float* o_m = out;
    float* o_d = out + (size_t)NM * OD;

    h16 *mfh,*dfh,*xm,*xd,*ad,*ad2,*hm,*hd,*qd,*ud,*basem;
    h16 *wm,*wd,*w1mdl,*w1mdr,*w1dml,*w1dmr,*w2mdl,*w2mdr,*w2dml,*w2dmr;
    int *cnt_m,*cnt_d,*off_m,*off_d,*cur_m,*cur_d,*csr_src,*csr_dst;
    SYM(mfh,g_mf); SYM(dfh,g_df);
    SYM(xm,g_xm); SYM(xd,g_xd);
    SYM(ad,g_ad); SYM(ad2,g_ad2);
    SYM(hm,g_hm); SYM(hd,g_hd);
    SYM(qd,g_qd); SYM(ud,g_ud); SYM(basem,g_base);
    SYM(wm,g_wm); SYM(wd,g_wd);
    SYM(w1mdl,g_w1mdl); SYM(w1mdr,g_w1mdr); SYM(w1dml,g_w1dml); SYM(w1dmr,g_w1dmr);
    SYM(w2mdl,g_w2mdl); SYM(w2mdr,g_w2mdr); SYM(w2dml,g_w2dml); SYM(w2dmr,g_w2dmr);
    SYM(cnt_m,g_cnt_m); SYM(cnt_d,g_cnt_d); SYM(off_m,g_off_m); SYM(off_d,g_off_d);
    SYM(cur_m,g_cur_m); SYM(cur_d,g_cur_d); SYM(csr_src,g_csr_src); SYM(csr_dst,g_csr_dst);

    cudaFuncSetAttribute(mma_gemm_batched, cudaFuncAttributeMaxDynamicSharedMemorySize, GEMM_SMEM_BYTES);

    // ---- fork s2: CSR chain overlaps with converts+encoders ----
    cudaEventRecord(aux.ev[0], ms);
    cudaStreamWaitEvent(s2, aux.ev[0], 0);
    zero_kernel<<<(NM + 255)/256, 256, 0, s2>>>(cnt_m, NM, cnt_d, ND);
    count_edges_kernel<<<(NE + 255) / 256, 256, 0, s2>>>(esrc, edst, cnt_m, cnt_d, NE);
    exscan2_kernel<<<2, 1024, 0, s2>>>(cnt_d, off_d, cur_d, ND, cnt_m, off_m, cur_m, NM);
    fill_csr_kernel<<<(NE + 255) / 256, 256, 0, s2>>>(esrc, edst, cur_m, cur_d, csr_src, csr_dst, NE);
    cudaEventRecord(aux.ev[1], s2);   // CSR ready

    // ---- main: one merged convert launch ----
    {
        CvtSet cs;
        const float* xs[12] = {mf, df, Wm, Wd, W1mdl, W1mdr, W1dml, W1dmr,
                               W2mdl, W2mdr, W2dml, W2dmr};
        h16* hs[12] = {mfh, dfh, wm, wd, w1mdl, w1mdr, w1dml, w1dmr,
                       w2mdl, w2mdr, w2dml, w2dmr};
        int n4s[12] = {NM*FIN/4, ND*FIN/4, FIN*HD/4, FIN*HD/4,
                       HD*H1/4, HD*H1/4, HD*H1/4, HD*H1/4,
                       H1*OD/4, H1*OD/4, H1*OD/4, H1*OD/4};
        int run = 0;
        for (int i = 0; i < 12; i++){
            cs.x[i] = xs[i]; cs.h[i] = hs[i]; cs.start[i] = run; run += n4s[i];
        }
        cs.start[12] = run;
        cvt_kernel<<<(run + 255)/256, 256, 0, ms>>>(cs);
    }

    // ---- main: L1 encoders ----
    {
        GemmDesc ds[2] = {
            mk_desc(mfh, wm, FIN, 0,0, 0,
                    NM, HD, bm, memb, mid, nullptr, xm, F_BIAS|F_GATH|F_HALF),
            mk_desc(dfh, wd, FIN, 0,0, 0,
                    ND, HD, bd, demb, did, nullptr, xd, F_BIAS|F_GATH|F_HALF)
        };
        launch_batch(ds, 2, ms);
    }

    // join: CSR ready before first gather
    cudaStreamWaitEvent(ms, aux.ev[1], 0);

    // ---- main: layer1 md aggregation ----
    seg_mean_kernel<HD><<<ND, HD/4, 0, ms>>>(xm, off_d, csr_src, ad);

    // ---- main: Group B: L1md-dual + qd + base_m ----
    {
        GemmDesc ds[3] = {
            mk_desc(ad, w1mdl, HD, xd, w1mdr, HD,
                    ND, H1, b1md, nullptr, nullptr, nullptr, hd, F_BIAS|F_RELU|F_HALF),
            mk_desc(xd, w1dml, HD, 0,0, 0,
                    ND, H1, nullptr, nullptr, nullptr, nullptr, qd, F_HALF),
            mk_desc(xm, w1dmr, HD, 0,0, 0,
                    NM, H1, b1dm, nullptr, nullptr, nullptr, basem, F_BIAS|F_HALF)
        };
        launch_batch(ds, 3, ms);
    }

    // ---- main: h_m = relu(base + mean(q_d)); layer2 md aggregation ----
    seg_relu_kernel<H1><<<NM, H1/4, 0, ms>>>(qd, basem, off_m, csr_dst, hm);
    seg_mean_kernel<H1><<<ND, H1/4, 0, ms>>>(hm, off_d, csr_src, ad2);

    // ---- main: Group C: L2md-dual + ud + o_m base ----
    {
        GemmDesc ds[3] = {
            mk_desc(ad2, w2mdl, H1, hd, w2mdr, H1,
                    ND, OD, b2md, nullptr, nullptr, o_d, nullptr, F_BIAS),
            mk_desc(hd, w2dml, H1, 0,0, 0,
                    ND, OD, nullptr, nullptr, nullptr, nullptr, ud, F_HALF),
            mk_desc(hm, w2dmr, H1, 0,0, 0,
                    NM, OD, b2dm, nullptr, nullptr, o_m, nullptr, F_BIAS)
        };
        launch_batch(ds, 3, ms);
    }

    // ---- main: o_m += mean(ud over incident diseases) ----
    seg_mean_acc_kernel<OD><<<NM, OD/4, 0, ms>>>(ud, off_m, csr_dst, o_m);
}

// round 17
// speedup vs baseline: 1.0358x; 1.0053x over previous
#include <cuda_runtime.h>
#include <cuda_fp16.h>
#include <cstdint>

#define NM 20000
#define ND 8000
#define NE 200000
#define FIN 384
#define HD 512
#define H1 512
#define OD 256

typedef __half  h16;
typedef __half2 h162;

// ---------------- scratch (device globals) ----------------
__device__ h16 g_mf[NM*FIN];
__device__ h16 g_df[ND*FIN];
__device__ h16 g_xm[NM*HD];
__device__ h16 g_xd[ND*HD];
__device__ h16 g_ad[ND*HD];
__device__ h16 g_ad2[ND*H1];
__device__ h16 g_hm[NM*H1];
__device__ h16 g_hd[ND*H1];
__device__ h16 g_qd[ND*H1];
__device__ h16 g_base[NM*H1];
__device__ h16 g_ud[ND*OD];
__device__ h16 g_wm[FIN*HD], g_wd[FIN*HD];
__device__ h16 g_w1mdl[HD*H1], g_w1mdr[HD*H1];
__device__ h16 g_w1dml[HD*H1], g_w1dmr[HD*H1];
__device__ h16 g_w2mdl[H1*OD], g_w2mdr[H1*OD];
__device__ h16 g_w2dml[H1*OD], g_w2dmr[H1*OD];
__device__ int g_cnt_m[NM], g_cnt_d[ND];
__device__ int g_off_m[NM+1], g_off_d[ND+1];
__device__ int g_cur_m[NM], g_cur_d[ND];
__device__ int g_csr_src[NE];
__device__ int g_csr_dst[NE];

// ---------------- PTX helpers ----------------
__device__ __forceinline__ void ldsm_x4(uint32_t& r0,uint32_t& r1,uint32_t& r2,uint32_t& r3,uint32_t a){
    asm volatile("ldmatrix.sync.aligned.m8n8.x4.shared.b16 {%0,%1,%2,%3},[%4];"
                 :"=r"(r0),"=r"(r1),"=r"(r2),"=r"(r3):"r"(a));
}
__device__ __forceinline__ void ldsm_x4t(uint32_t& r0,uint32_t& r1,uint32_t& r2,uint32_t& r3,uint32_t a){
    asm volatile("ldmatrix.sync.aligned.m8n8.x4.trans.shared.b16 {%0,%1,%2,%3},[%4];"
                 :"=r"(r0),"=r"(r1),"=r"(r2),"=r"(r3):"r"(a));
}
__device__ __forceinline__ void mma_f16(float* c, const uint32_t* a, uint32_t b0, uint32_t b1){
    asm volatile("mma.sync.aligned.m16n8k16.row.col.f32.f16.f16.f32 "
        "{%0,%1,%2,%3},{%4,%5,%6,%7},{%8,%9},{%0,%1,%2,%3};"
        :"+f"(c[0]),"+f"(c[1]),"+f"(c[2]),"+f"(c[3])
        :"r"(a[0]),"r"(a[1]),"r"(a[2]),"r"(a[3]),"r"(b0),"r"(b1));
}
__device__ __forceinline__ void cpa16(uint32_t d, const void* s, bool p){
    int sz = p ? 16 : 0;
    asm volatile("cp.async.cg.shared.global [%0],[%1],16,%2;"::"r"(d),"l"(s),"r"(sz));
}

// smem geometry (fp16 elements); 2-stage pipeline (R13-proven)
#define SA 40
#define SB 136
#define ASZ (128*SA)
#define BSZ (32*SB)
#define STAGE_E (ASZ + BSZ)
#define GEMM_SMEM_BYTES (2*STAGE_E*2)

// flags
#define F_BIAS  1
#define F_RELU  2
#define F_GATH  4
#define F_HALF  8

struct GemmDesc {
    const h16 *A1,*B1;
    const h16 *A2,*B2;
    int K1, K2, M, N;
    const float *bias, *Demb; const int* idx;
    float* C; h16 *Ch;
    int flags;
    int start, tx;
};
struct GemmBatch { GemmDesc g[3]; int n; };

// ---------------- batched fp16 tensor-core GEMM (R13-proven, 2-stage) ----------------
__global__ __launch_bounds__(256,2) void mma_gemm_batched(GemmBatch gb)
{
    extern __shared__ h16 smem[];
    uint32_t sbase = (uint32_t)__cvta_generic_to_shared(smem);
    const int tid  = threadIdx.x;
    const int lane = tid & 31;
    const int wid  = tid >> 5;
    const int wm   = (wid & 3) * 32;
    const int wn   = (wid >> 2) * 64;

    int gi = 0;
    if (gb.n > 1 && (int)blockIdx.x >= gb.g[1].start) gi = 1;
    if (gb.n > 2 && (int)blockIdx.x >= gb.g[2].start) gi = 2;
    const GemmDesc d = gb.g[gi];

    const int rel = blockIdx.x - d.start;
    const int bn  = (rel % d.tx) * 128;
    const int bm  = (rel / d.tx) * 128;
    const int M = d.M, N = d.N;
    const int S1 = d.K1 >> 5, S2 = d.K2 >> 5, S = S1 + S2;

    float acc[2][8][4];
#pragma unroll
    for (int i=0;i<2;i++)
#pragma unroll
        for (int j=0;j<8;j++)
#pragma unroll
            for (int k=0;k<4;k++) acc[i][j][k] = 0.f;

    auto prefetch = [&](int s){
        const h16 *A,*B; int K,k0;
        if (s < S1){ A=d.A1; B=d.B1; K=d.K1; k0=s<<5; }
        else       { A=d.A2; B=d.B2; K=d.K2; k0=(s-S1)<<5; }
        uint32_t sb = sbase + (uint32_t)((s&1)*STAGE_E*2);
        int ar = tid>>2, ac = (tid&3)*8;
#pragma unroll
        for (int i=0;i<2;i++){
            int row = bm + ar + 64*i;
            bool ok = row < M;
            int sr = ok ? row : 0;
            uint32_t dd = sb + (uint32_t)(((ar+64*i)*SA + ac)*2);
            cpa16(dd, A + (size_t)sr*K + k0 + ac, ok);
        }
        int bk = tid>>4, bc = (tid&15)*8;
#pragma unroll
        for (int i=0;i<2;i++){
            int k = bk + 16*i;
            uint32_t dd = sb + (uint32_t)((ASZ + k*SB + bc)*2);
            cpa16(dd, B + (size_t)(k0 + k)*N + bn + bc, true);
        }
        asm volatile("cp.async.commit_group;");
    };

    prefetch(0);
    for (int s=0;s<S;s++){
        if (s+1 < S){
            prefetch(s+1);
            asm volatile("cp.async.wait_group 1;");
        } else {
            asm volatile("cp.async.wait_group 0;");
        }
        __syncthreads();
        uint32_t sb = sbase + (uint32_t)((s&1)*STAGE_E*2);
#pragma unroll
        for (int kk=0;kk<2;kk++){
            const int k16 = kk*16;
            const int loff = (lane>>1)&8;
            uint32_t ah[2][4];
#pragma unroll
            for (int mf=0;mf<2;mf++){
                uint32_t a = sb + (uint32_t)((((wm + mf*16 + (lane&15))*SA) + k16 + loff)*2);
                ldsm_x4(ah[mf][0],ah[mf][1],ah[mf][2],ah[mf][3], a);
            }
#pragma unroll
            for (int nb=0;nb<4;nb++){
                uint32_t a = sb + (uint32_t)((ASZ + (k16 + (lane&15))*SB + wn + nb*16 + loff)*2);
                uint32_t bh[4];
                ldsm_x4t(bh[0],bh[1],bh[2],bh[3], a);
#pragma unroll
                for (int h=0;h<2;h++){
#pragma unroll
                    for (int mf=0;mf<2;mf++){
                        mma_f16(acc[mf][nb*2+h], ah[mf], bh[2*h], bh[2*h+1]);
                    }
                }
            }
        }
        __syncthreads();
    }

    const int fl = d.flags;
#pragma unroll
    for (int mf=0;mf<2;mf++){
#pragma unroll
        for (int nf=0;nf<8;nf++){
            int col = bn + wn + nf*8 + (lane&3)*2;
#pragma unroll
            for (int half=0;half<2;half++){
                int row = bm + wm + mf*16 + (lane>>2) + half*8;
                if (row >= M) continue;
                float v0 = acc[mf][nf][half*2+0];
                float v1 = acc[mf][nf][half*2+1];
                if (fl & F_BIAS){ v0 += __ldg(&d.bias[col]); v1 += __ldg(&d.bias[col+1]); }
                if (fl & F_GATH){
                    int g = __ldg(&d.idx[row]);
                    const float* e = d.Demb + (size_t)g*N + col;
                    v0 += __ldg(&e[0]); v1 += __ldg(&e[1]);
                }
                if (fl & F_RELU){ v0 = fmaxf(v0,0.f); v1 = fmaxf(v1,0.f); }
                if (fl & F_HALF){
                    *(h162*)(d.Ch + (size_t)row*N + col) =
                        __halves2half2(__float2half_rn(v0), __float2half_rn(v1));
                } else {
                    float2 o; o.x=v0; o.y=v1;
                    *(float2*)(d.C + (size_t)row*N + col) = o;
                }
            }
        }
    }
}

// ---------------- single merged convert fp32 -> fp16 (12 segments) ----------------
struct CvtSet { const float* x[12]; h16* h[12]; int start[13]; };
__global__ void cvt_kernel(CvtSet cs)
{
    int q = blockIdx.x*blockDim.x + threadIdx.x;
    if (q >= cs.start[12]) return;
    int z = 0;
#pragma unroll
    for (int i = 1; i < 12; i++) if (q >= cs.start[i]) z = i;
    int off = q - cs.start[z];
    float4 v = ((const float4*)cs.x[z])[off];
    h162* H = (h162*)cs.h[z];
    H[2*off]   = __halves2half2(__float2half_rn(v.x), __float2half_rn(v.y));
    H[2*off+1] = __halves2half2(__float2half_rn(v.z), __float2half_rn(v.w));
}

// ---------------- CSR build ----------------
__global__ void zero_kernel(int* a, int na, int* b, int nb)
{
    int i = blockIdx.x*blockDim.x + threadIdx.x;
    if (i < na) a[i] = 0;
    if (i < nb) b[i] = 0;
}

__global__ void count_edges_kernel(const int* __restrict__ src, const int* __restrict__ dst,
                                   int* __restrict__ cm, int* __restrict__ cd, int E)
{
    int i = blockIdx.x * blockDim.x + threadIdx.x;
    if (i < E) {
        atomicAdd(&cd[dst[i]], 1);
        atomicAdd(&cm[src[i]], 1);
    }
}

__global__ void exscan2_kernel(const int* __restrict__ cnt_d, int* __restrict__ off_d, int* __restrict__ cur_d, int n_d,
                               const int* __restrict__ cnt_m, int* __restrict__ off_m, int* __restrict__ cur_m, int n_m)
{
    const int* cnt; int* off; int* cur; int n;
    if (blockIdx.x == 0){ cnt = cnt_d; off = off_d; cur = cur_d; n = n_d; }
    else               { cnt = cnt_m; off = off_m; cur = cur_m; n = n_m; }
    __shared__ int wsum[32];
    int t = threadIdx.x;
    int chunk = (n + 1023) >> 10;
    int s = t * chunk; if (s > n) s = n;
    int e = s + chunk; if (e > n) e = n;
    int sum = 0;
    for (int i = s; i < e; i++) sum += cnt[i];
    int lane = t & 31, w = t >> 5;
    int v = sum;
#pragma unroll
    for (int dd = 1; dd < 32; dd <<= 1){
        int o = __shfl_up_sync(0xFFFFFFFFu, v, dd);
        if (lane >= dd) v += o;
    }
    if (lane == 31) wsum[w] = v;
    __syncthreads();
    if (w == 0){
        int x = wsum[lane];
#pragma unroll
        for (int dd = 1; dd < 32; dd <<= 1){
            int o = __shfl_up_sync(0xFFFFFFFFu, x, dd);
            if (lane >= dd) x += o;
        }
        wsum[lane] = x;
    }
    __syncthreads();
    int run = v - sum + (w > 0 ? wsum[w-1] : 0);
    for (int i = s; i < e; i++){
        off[i] = run; cur[i] = run; run += cnt[i];
    }
    if (t == 1023) off[n] = run;
}

__global__ void fill_csr_kernel(const int* __restrict__ src, const int* __restrict__ dst,
                                int* __restrict__ cur_m, int* __restrict__ cur_d,
                                int* __restrict__ csr_src, int* __restrict__ csr_dst, int E)
{
    int i = blockIdx.x * blockDim.x + threadIdx.x;
    if (i < E) {
        int m = src[i], d = dst[i];
        int p = atomicAdd(&cur_d[d], 1);
        csr_src[p] = m;
        int q = atomicAdd(&cur_m[m], 1);
        csr_dst[q] = d;
    }
}

// ---------------- segment mean: fp16-in -> fp16-out ----------------
template<int WIDTH>
__global__ void seg_mean_kernel(const h16* __restrict__ X,
                                const int* __restrict__ off, const int* __restrict__ nbr,
                                h16* __restrict__ C)
{
    int row = blockIdx.x;
    int t = threadIdx.x;
    int s = off[row], e = off[row + 1];
    float a0=0.f,a1=0.f,a2=0.f,a3=0.f;
    float b0=0.f,b1=0.f,b2=0.f,b3=0.f;
    int i = s;
    for (; i + 2 <= e; i += 2){
        int n0 = __ldg(&nbr[i]);
        int n1 = __ldg(&nbr[i+1]);
        const h162* p0 = (const h162*)(X + (size_t)n0*WIDTH);
        const h162* p1 = (const h162*)(X + (size_t)n1*WIDTH);
        float2 u0 = __half22float2(__ldg(&p0[2*t]));
        float2 u1 = __half22float2(__ldg(&p0[2*t+1]));
        float2 w0 = __half22float2(__ldg(&p1[2*t]));
        float2 w1 = __half22float2(__ldg(&p1[2*t+1]));
        a0 += u0.x; a1 += u0.y; a2 += u1.x; a3 += u1.y;
        b0 += w0.x; b1 += w0.y; b2 += w1.x; b3 += w1.y;
    }
    if (i < e){
        int n0 = __ldg(&nbr[i]);
        const h162* p0 = (const h162*)(X + (size_t)n0*WIDTH);
        float2 u0 = __half22float2(__ldg(&p0[2*t]));
        float2 u1 = __half22float2(__ldg(&p0[2*t+1]));
        a0 += u0.x; a1 += u0.y; a2 += u1.x; a3 += u1.y;
    }
    a0 += b0; a1 += b1; a2 += b2; a3 += b3;
    float inv = (e > s) ? 1.0f/(float)(e - s) : 0.0f;
    a0 *= inv; a1 *= inv; a2 *= inv; a3 *= inv;
    h162* oc = (h162*)(C + (size_t)row*WIDTH);
    oc[2*t]   = __halves2half2(__float2half_rn(a0), __float2half_rn(a1));
    oc[2*t+1] = __halves2half2(__float2half_rn(a2), __float2half_rn(a3));
}

// ---------------- seg mean (fp16 msgs) + fp16 base + relu -> fp16 out ----------------
template<int WIDTH>
__global__ void seg_relu_kernel(const h16* __restrict__ Q, const h16* __restrict__ Base,
                                const int* __restrict__ off, const int* __restrict__ nbr,
                                h16* __restrict__ C)
{
    int row = blockIdx.x;
    int t = threadIdx.x;
    int s = off[row], e = off[row + 1];
    float a0=0.f,a1=0.f,a2=0.f,a3=0.f;
    float b0=0.f,b1=0.f,b2=0.f,b3=0.f;
    int i = s;
    for (; i + 2 <= e; i += 2){
        int n0 = __ldg(&nbr[i]);
        int n1 = __ldg(&nbr[i+1]);
        const h162* p0 = (const h162*)(Q + (size_t)n0*WIDTH);
        const h162* p1 = (const h162*)(Q + (size_t)n1*WIDTH);
        float2 u0 = __half22float2(__ldg(&p0[2*t]));
        float2 u1 = __half22float2(__ldg(&p0[2*t+1]));
        float2 w0 = __half22float2(__ldg(&p1[2*t]));
        float2 w1 = __half22float2(__ldg(&p1[2*t+1]));
        a0 += u0.x; a1 += u0.y; a2 += u1.x; a3 += u1.y;
        b0 += w0.x; b1 += w0.y; b2 += w1.x; b3 += w1.y;
    }
    if (i < e){
        int n0 = __ldg(&nbr[i]);
        const h162* p0 = (const h162*)(Q + (size_t)n0*WIDTH);
        float2 u0 = __half22float2(__ldg(&p0[2*t]));
        float2 u1 = __half22float2(__ldg(&p0[2*t+1]));
        a0 += u0.x; a1 += u0.y; a2 += u1.x; a3 += u1.y;
    }
    a0 += b0; a1 += b1; a2 += b2; a3 += b3;
    float inv = (e > s) ? 1.0f/(float)(e - s) : 0.0f;
    const h162* bp = (const h162*)(Base + (size_t)row*WIDTH);
    float2 bb0 = __half22float2(__ldg(&bp[2*t]));
    float2 bb1 = __half22float2(__ldg(&bp[2*t+1]));
    float x0 = fmaxf(bb0.x + a0*inv, 0.f);
    float x1 = fmaxf(bb0.y + a1*inv, 0.f);
    float x2 = fmaxf(bb1.x + a2*inv, 0.f);
    float x3 = fmaxf(bb1.y + a3*inv, 0.f);
    h162* oc = (h162*)(C + (size_t)row*WIDTH);
    oc[2*t]   = __halves2half2(__float2half_rn(x0), __float2half_rn(x1));
    oc[2*t+1] = __halves2half2(__float2half_rn(x2), __float2half_rn(x3));
}

// ---------------- seg mean: fp16-in, accumulate into f32 out ----------------
template <int WIDTH>
__global__ void seg_mean_acc_kernel(const h16* __restrict__ X, const int* __restrict__ off,
                                    const int* __restrict__ nbr, float* __restrict__ C)
{
    int row = blockIdx.x;
    int t = threadIdx.x;
    int s = off[row], e = off[row + 1];
    float a0=0.f,a1=0.f,a2=0.f,a3=0.f;
    float b0=0.f,b1=0.f,b2=0.f,b3=0.f;
    int i = s;
    for (; i + 2 <= e; i += 2){
        int n0 = __ldg(&nbr[i]);
        int n1 = __ldg(&nbr[i+1]);
        const h162* p0 = (const h162*)(X + (size_t)n0*WIDTH);
        const h162* p1 = (const h162*)(X + (size_t)n1*WIDTH);
        float2 u0 = __half22float2(__ldg(&p0[2*t]));
        float2 u1 = __half22float2(__ldg(&p0[2*t+1]));
        float2 w0 = __half22float2(__ldg(&p1[2*t]));
        float2 w1 = __half22float2(__ldg(&p1[2*t+1]));
        a0 += u0.x; a1 += u0.y; a2 += u1.x; a3 += u1.y;
        b0 += w0.x; b1 += w0.y; b2 += w1.x; b3 += w1.y;
    }
    if (i < e){
        int n0 = __ldg(&nbr[i]);
        const h162* p0 = (const h162*)(X + (size_t)n0*WIDTH);
        float2 u0 = __half22float2(__ldg(&p0[2*t]));
        float2 u1 = __half22float2(__ldg(&p0[2*t+1]));
        a0 += u0.x; a1 += u0.y; a2 += u1.x; a3 += u1.y;
    }
    a0 += b0; a1 += b1; a2 += b2; a3 += b3;
    float inv = (e > s) ? 1.0f / (float)(e - s) : 0.0f;
    float4* cp = (float4*)(C + (size_t)row * WIDTH) + t;
    float4 o = *cp;
    o.x += a0*inv; o.y += a1*inv; o.z += a2*inv; o.w += a3*inv;
    *cp = o;
}

// ---------------- host orchestration ----------------
#define SYM(p, s) cudaGetSymbolAddress((void**)&(p), s)

static inline GemmDesc mk_desc(
    const h16* A1, const h16* B1, int K1,
    const h16* A2, const h16* B2, int K2,
    int M, int N, const float* bias, const float* Demb, const int* idx,
    float* C, h16* Ch, int flags)
{
    GemmDesc d;
    d.A1=A1; d.B1=B1; d.K1=K1;
    d.A2=A2; d.B2=B2; d.K2=K2;
    d.M=M; d.N=N; d.bias=bias; d.Demb=Demb; d.idx=idx;
    d.C=C; d.Ch=Ch; d.flags=flags;
    d.start=0; d.tx=N/128;
    return d;
}

static inline void launch_batch(GemmDesc* descs, int n, cudaStream_t st)
{
    GemmBatch gb;
    int total = 0;
    for (int i = 0; i < n; i++){
        descs[i].start = total;
        total += descs[i].tx * ((descs[i].M + 127)/128);
        gb.g[i] = descs[i];
    }
    for (int i = n; i < 3; i++){ gb.g[i] = descs[n-1]; gb.g[i].start = 0x7FFFFFFF; }
    gb.n = n;
    mma_gemm_batched<<<total, 256, GEMM_SMEM_BYTES, st>>>(gb);
}

// static aux resources (created on first, uncaptured, call)
struct Aux {
    cudaStream_t s2;
    cudaEvent_t ev[5];
    Aux(){
        cudaStreamCreateWithFlags(&s2, cudaStreamNonBlocking);
        for (int i = 0; i < 5; i++)
            cudaEventCreateWithFlags(&ev[i], cudaEventDisableTiming);
    }
};

extern "C" void kernel_launch(void* const* d_in, const int* in_sizes, int n_in,
                              void* d_out, int out_size)
{
    static Aux aux;

    cudaStream_t ms = cudaStreamPerThread;
    {
        cudaStreamCaptureStatus st = cudaStreamCaptureStatusNone;
        if (cudaStreamIsCapturing(cudaStreamPerThread, &st) == cudaSuccess &&
            st == cudaStreamCaptureStatusActive) {
            ms = cudaStreamPerThread;
        } else {
            cudaGetLastError();
            st = cudaStreamCaptureStatusNone;
            if (cudaStreamIsCapturing(cudaStreamLegacy, &st) == cudaSuccess &&
                st == cudaStreamCaptureStatusActive) {
                ms = cudaStreamLegacy;
            }
            cudaGetLastError();
        }
    }
    cudaStream_t s2 = aux.s2;

    const float* mf   = (const float*)d_in[0];
    const float* df   = (const float*)d_in[1];
    const int*   mid  = (const int*)d_in[2];
    const int*   did  = (const int*)d_in[3];
    const int*   esrc = (const int*)d_in[4];
    const int*   edst = (const int*)d_in[5];
    const float* Wm   = (const float*)d_in[6];
    const float* bm   = (const float*)d_in[7];
    const float* Wd   = (const float*)d_in[8];
    const float* bd   = (const float*)d_in[9];
    const float* memb = (const float*)d_in[10];
    const float* demb = (const float*)d_in[11];
    const float* W1mdl = (const float*)d_in[12];
    const float* b1md  = (const float*)d_in[13];
    const float* W1mdr = (const float*)d_in[14];
    const float* W1dml = (const float*)d_in[15];
    const float* b1dm  = (const float*)d_in[16];
    const float* W1dmr = (const float*)d_in[17];
    const float* W2mdl = (const float*)d_in[18];
    const float* b2md  = (const float*)d_in[19];
    const float* W2mdr = (const float*)d_in[20];
    const float* W2dml = (const float*)d_in[21];
    const float* b2dm  = (const float*)d_in[22];
    const float* W2dmr = (const float*)d_in[23];

    float* out = (float*)d_out;
    float* o_m = out;
    float* o_d = out + (size_t)NM * OD;

    h16 *mfh,*dfh,*xm,*xd,*ad,*ad2,*hm,*hd,*qd,*ud,*basem;
    h16 *wm,*wd,*w1mdl,*w1mdr,*w1dml,*w1dmr,*w2mdl,*w2mdr,*w2dml,*w2dmr;
    int *cnt_m,*cnt_d,*off_m,*off_d,*cur_m,*cur_d,*csr_src,*csr_dst;
    SYM(mfh,g_mf); SYM(dfh,g_df);
    SYM(xm,g_xm); SYM(xd,g_xd);
    SYM(ad,g_ad); SYM(ad2,g_ad2);
    SYM(hm,g_hm); SYM(hd,g_hd);
    SYM(qd,g_qd); SYM(ud,g_ud); SYM(basem,g_base);
    SYM(wm,g_wm); SYM(wd,g_wd);
    SYM(w1mdl,g_w1mdl); SYM(w1mdr,g_w1mdr); SYM(w1dml,g_w1dml); SYM(w1dmr,g_w1dmr);
    SYM(w2mdl,g_w2mdl); SYM(w2mdr,g_w2mdr); SYM(w2dml,g_w2dml); SYM(w2dmr,g_w2dmr);
    SYM(cnt_m,g_cnt_m); SYM(cnt_d,g_cnt_d); SYM(off_m,g_off_m); SYM(off_d,g_off_d);
    SYM(cur_m,g_cur_m); SYM(cur_d,g_cur_d); SYM(csr_src,g_csr_src); SYM(csr_dst,g_csr_dst);

    cudaFuncSetAttribute(mma_gemm_batched, cudaFuncAttributeMaxDynamicSharedMemorySize, GEMM_SMEM_BYTES);

    // ---- fork s2: CSR chain overlaps with converts+encoders ----
    cudaEventRecord(aux.ev[0], ms);
    cudaStreamWaitEvent(s2, aux.ev[0], 0);
    zero_kernel<<<(NM + 255)/256, 256, 0, s2>>>(cnt_m, NM, cnt_d, ND);
    count_edges_kernel<<<(NE + 255) / 256, 256, 0, s2>>>(esrc, edst, cnt_m, cnt_d, NE);
    exscan2_kernel<<<2, 1024, 0, s2>>>(cnt_d, off_d, cur_d, ND, cnt_m, off_m, cur_m, NM);
    fill_csr_kernel<<<(NE + 255) / 256, 256, 0, s2>>>(esrc, edst, cur_m, cur_d, csr_src, csr_dst, NE);
    // (CSR ready stays on s2; its first consumer is s2's seg_mean below)

    // ---- main: one merged convert launch ----
    {
        CvtSet cs;
        const float* xs[12] = {mf, df, Wm, Wd, W1mdl, W1mdr, W1dml, W1dmr,
                               W2mdl, W2mdr, W2dml, W2dmr};
        h16* hs[12] = {mfh, dfh, wm, wd, w1mdl, w1mdr, w1dml, w1dmr,
                       w2mdl, w2mdr, w2dml, w2dmr};
        int n4s[12] = {NM*FIN/4, ND*FIN/4, FIN*HD/4, FIN*HD/4,
                       HD*H1/4, HD*H1/4, HD*H1/4, HD*H1/4,
                       H1*OD/4, H1*OD/4, H1*OD/4, H1*OD/4};
        int run = 0;
        for (int i = 0; i < 12; i++){
            cs.x[i] = xs[i]; cs.h[i] = hs[i]; cs.start[i] = run; run += n4s[i];
        }
        cs.start[12] = run;
        cvt_kernel<<<(run + 255)/256, 256, 0, ms>>>(cs);
    }

    // ---- main: L1 encoders ----
    {
        GemmDesc ds[2] = {
            mk_desc(mfh, wm, FIN, 0,0, 0,
                    NM, HD, bm, memb, mid, nullptr, xm, F_BIAS|F_GATH|F_HALF),
            mk_desc(dfh, wd, FIN, 0,0, 0,
                    ND, HD, bd, demb, did, nullptr, xd, F_BIAS|F_GATH|F_HALF)
        };
        launch_batch(ds, 2, ms);
    }
    cudaEventRecord(aux.ev[1], ms);   // xm/xd ready

    // ---- s2: layer1 md aggregation (needs CSR [s2-local] + xm [ev1]) ----
    cudaStreamWaitEvent(s2, aux.ev[1], 0);
    seg_mean_kernel<HD><<<ND, HD/4, 0, s2>>>(xm, off_d, csr_src, ad);
    cudaEventRecord(aux.ev[2], s2);   // ad ready

    // ---- main (concurrent): qd + base GEMMs (no ad dependency) ----
    {
        GemmDesc ds[2] = {
            mk_desc(xd, w1dml, HD, 0,0, 0,
                    ND, H1, nullptr, nullptr, nullptr, nullptr, qd, F_HALF),
            mk_desc(xm, w1dmr, HD, 0,0, 0,
                    NM, H1, b1dm, nullptr, nullptr, nullptr, basem, F_BIAS|F_HALF)
        };
        launch_batch(ds, 2, ms);
    }

    // ---- main: L1md-dual GEMM (needs ad from ev2) ----
    cudaStreamWaitEvent(ms, aux.ev[2], 0);
    {
        GemmDesc ds[1] = {
            mk_desc(ad, w1mdl, HD, xd, w1mdr, HD,
                    ND, H1, b1md, nullptr, nullptr, nullptr, hd, F_BIAS|F_RELU|F_HALF)
        };
        launch_batch(ds, 1, ms);
    }

    // ---- main: h_m = relu(base + mean(q_d)); layer2 md aggregation ----
    seg_relu_kernel<H1><<<NM, H1/4, 0, ms>>>(qd, basem, off_m, csr_dst, hm);
    seg_mean_kernel<H1><<<ND, H1/4, 0, ms>>>(hm, off_d, csr_src, ad2);

    // ---- main: Group C: L2md-dual + ud + o_m base ----
    {
        GemmDesc ds[3] = {
            mk_desc(ad2, w2mdl, H1, hd, w2mdr, H1,
                    ND, OD, b2md, nullptr, nullptr, o_d, nullptr, F_BIAS),
            mk_desc(hd, w2dml, H1, 0,0, 0,
                    ND, OD, nullptr, nullptr, nullptr, nullptr, ud, F_HALF),
            mk_desc(hm, w2dmr, H1, 0,0, 0,
                    NM, OD, b2dm, nullptr, nullptr, o_m, nullptr, F_BIAS)
        };
        launch_batch(ds, 3, ms);
    }

    // ---- main: o_m += mean(ud over incident diseases) ----
    seg_mean_acc_kernel<OD><<<NM, OD/4, 0, ms>>>(ud, off_m, csr_dst, o_m);
}